// round 9
// baseline (speedup 1.0000x reference)
#include <cuda_runtime.h>
#include <cstdint>

// Problem constants: N=4096 nodes, T=128 timesteps, D=64, E=131072 edges.
#define NN 4096
#define TT 128
#define DD 64
#define NSUB 8
#define SUBCAP 32                 // per-(dst,sub) ~ Poisson(4); P(>32) ~ 1e-18
#define CAP (NSUB * SUBCAP)       // 256 slots per dst
#define NBLK 1184                 // 8 blocks/SM x 148 SMs -> guaranteed co-resident
#define NTHR 128
#define NWARP (NTHR / 32)
#define GTH (NBLK * NTHR)         // 151552 threads

typedef unsigned long long u64;

// ---------------- scratch (device globals; zero-init at load; self-cleaning) ----------------
__device__ float g_rs[NN];           // row-sum EXCESS over 1; reset phase1, accumulated phase2
__device__ int   g_scnt[NN * NSUB];  // sub-counters; reset by phase2 after reading
__device__ u64   g_bkt[NN * CAP];    // packed bucket: (((src<<18)|e) << 32) | w_bits
__device__ int   g_ccnt[NN];         // compacted winner count (overwritten each launch)
__device__ u64   g_csr[NN * CAP];    // packed CSR: (src << 32) | w_bits
__device__ u64   g_tickets;          // monotonic grid-barrier counter; NEVER reset (replay-safe)

__device__ __forceinline__ float tanh_fast(float x) {
    float y;
    asm("tanh.approx.f32 %0, %1;" : "=f"(y) : "f"(x));
    return y;
}

// Software grid barrier: barrier instance k consumes ticket window [k*NBLK,(k+1)*NBLK).
// A block cannot reach instance k+1 before instance k releases, so windows never mix.
__device__ __forceinline__ void grid_barrier() {
    __syncthreads();
    if (threadIdx.x == 0) {
        __threadfence();
        u64 tk = atomicAdd(&g_tickets, 1ULL);
        u64 target = (tk / NBLK + 1ULL) * NBLK;
        while (*((volatile u64*)&g_tickets) < target) { }
        __threadfence();
    }
    __syncthreads();
}

struct SmDD { u64 buf[NWARP][CAP]; int pos[NWARP]; };                    // dedup: 8.2 KB
struct SmFU { int ss[TT]; float sw[TT]; float ax[TT]; float4 w[DD / 4]; }; // fused: 1.8 KB
union  SmU  { SmDD dd; SmFU fu; };

__global__ void __launch_bounds__(NTHR, 8) k_all(
    const float* __restrict__ x, const int* __restrict__ ei,
    const float* __restrict__ ew, const float* __restrict__ wv,
    float4* __restrict__ out, int E)
{
    __shared__ SmU sm;
    int tid  = threadIdx.x;
    int gtid = blockIdx.x * NTHR + tid;
    int lane = tid & 31, wid = tid >> 5;

    // ================= phase 1: scatter edges into 8-way sharded dst buckets =================
    if (gtid < NN) g_rs[gtid] = 0.0f;       // reset before phase2 accumulates
    for (int e = gtid; e < E; e += GTH) {
        int src = ei[e];
        int dst = ei[E + e];
        int sub = e & (NSUB - 1);
        int p = atomicAdd(&g_scnt[dst * NSUB + sub], 1);
        if (p < SUBCAP)
            g_bkt[dst * CAP + sub * SUBCAP + p] =
                ((u64)(unsigned)((src << 18) | e) << 32) | (u64)__float_as_uint(ew[e]);
    }
    grid_barrier();

    // ================= phase 2: one warp per dst row: compact, dedup, row sums, CSR ==========
    for (int i = blockIdx.x * NWARP + wid; i < NN; i += NBLK * NWARP) {
        int cval = 0;
        if (lane < NSUB) {
            cval = min(g_scnt[i * NSUB + lane], SUBCAP);
            g_scnt[i * NSUB + lane] = 0;                 // self-clean for next replay
        }
        int c[NSUB], base[NSUB];
        int tot = 0;
        #pragma unroll
        for (int s = 0; s < NSUB; s++) {
            c[s] = __shfl_sync(0xffffffff, cval, s);
            base[s] = tot;
            tot += c[s];
        }
        if (lane == 0) sm.dd.pos[wid] = 0;

        #pragma unroll
        for (int slot = 0; slot < CAP; slot += 32) {     // dense compaction into smem
            int s = (slot + lane) >> 5;
            int l = (slot + lane) & 31;
            if (l < c[s]) sm.dd.buf[wid][base[s] + l] = g_bkt[i * CAP + slot + lane];
        }
        __syncwarp();

        for (int j = lane; j < tot; j += 32) {           // last-write-wins dedup
            u64 vj = sm.dd.buf[wid][j];
            int kj = (int)(vj >> 32);
            bool win = true;
            for (int k = 0; k < tot; k++) {
                int kk = (int)(sm.dd.buf[wid][k] >> 32);
                if (((kk ^ kj) >> 18) == 0 && kk > kj) win = false;  // same src, newer edge
            }
            if (win) {
                int src = kj >> 18;
                float wt = __uint_as_float((unsigned)vj);
                atomicAdd(&g_rs[src], wt);               // no-return -> RED, spread addresses
                int pos = atomicAdd(&sm.dd.pos[wid], 1); // order irrelevant to the gather
                g_csr[i * CAP + pos] = ((u64)(unsigned)src << 32) | (u64)__float_as_uint(wt);
            }
        }
        __syncwarp();
        if (lane == 0) g_ccnt[i] = sm.dd.pos[wid];
        __syncwarp();
    }
    grid_barrier();

    // ================= phase 3: SpMM + tanh epilogue, one row per block (strided) ============
    // d[i] = rsqrt(1+rs[i]); ax[i,t] = d[i]*( d[i]*x[i,t] + sum w*d[s]*x[s,t] )
    // out[i,t,d] = tanh(ax[i,t] * wv[d])
    if (tid < DD / 4) sm.fu.w[tid] = reinterpret_cast<const float4*>(wv)[tid];
    __syncthreads();
    for (int i = blockIdx.x; i < NN; i += NBLK) {
        int cnt = min(g_ccnt[i], TT);                    // dedup'd in-degree ~Poisson(32)
        float dinv = rsqrtf(1.0f + g_rs[i]);
        float acc = dinv * x[i * TT + tid];              // self-loop term
        if (tid < cnt) {
            u64 v = g_csr[i * CAP + tid];
            int s = (int)(v >> 32);
            sm.fu.ss[tid] = s;
            sm.fu.sw[tid] = __uint_as_float((unsigned)v) * rsqrtf(1.0f + g_rs[s]);
        }
        __syncthreads();
        #pragma unroll 4
        for (int j = 0; j < cnt; j++)
            acc = fmaf(sm.fu.sw[j], x[sm.fu.ss[j] * TT + tid], acc);
        sm.fu.ax[tid] = dinv * acc;
        __syncthreads();

        float4* outb = out + (size_t)i * (TT * DD / 4);
        float4  w4   = sm.fu.w[tid & 15];
        int     arow = tid >> 4;
        #pragma unroll
        for (int m = 0; m < 16; m++) {
            float a = sm.fu.ax[arow + 8 * m];
            float4 r;
            r.x = tanh_fast(a * w4.x);
            r.y = tanh_fast(a * w4.y);
            r.z = tanh_fast(a * w4.z);
            r.w = tanh_fast(a * w4.w);
            __stcs(outb + tid + 128 * m, r);
        }
        __syncthreads();                                 // protect ss/sw/ax before next refill
    }
}

extern "C" void kernel_launch(void* const* d_in, const int* in_sizes, int n_in,
                              void* d_out, int out_size) {
    const float* x  = (const float*)d_in[0];   // [4096,128] fp32
    const int*   ei = (const int*)d_in[1];     // [2,E] int32 (JAX x64 disabled)
    const float* ew = (const float*)d_in[2];   // [E] fp32
    const float* wv = (const float*)d_in[3];   // [1,64] fp32

    int E = in_sizes[2];
    k_all<<<NBLK, NTHR>>>(x, ei, ew, wv, (float4*)d_out, E);
    (void)n_in; (void)out_size;
}

// round 10
// speedup vs baseline: 1.2617x; 1.2617x over previous
#include <cuda_runtime.h>
#include <cstdint>

// Problem constants: N=4096 nodes, T=128 timesteps, D=64, E=131072 edges.
#define NN 4096
#define TT 128
#define DD 64
#define NSUB 8
#define SUBCAP 32                 // per-(dst,sub) ~ Poisson(4); P(>32) ~ 1e-18
#define CAP (NSUB * SUBCAP)       // 256 slots per dst
#define ROWS_PER_BLK 8            // k_dedup: one warp per dst row
#define CPAD 8                    // pad each sub-counter to its own 32B sector

typedef unsigned long long u64;

// ---------------- scratch (device globals; zero-init at load; self-cleaning) ----------------
__device__ float g_rs[NN];                    // row-sum EXCESS over 1; reset in k_bucket
__device__ int   g_scnt[NN * NSUB * CPAD];    // sector-padded sub-counters; reset by k_dedup
__device__ u64   g_bkt[NN * CAP];             // packed bucket: (((src<<18)|e) << 32) | w_bits
__device__ int   g_ccnt[NN];                  // compacted winner count (overwritten each launch)
__device__ u64   g_csr[NN * CAP];             // packed CSR: (src << 32) | w_bits

__device__ __forceinline__ float tanh_fast(float x) {
    float y;
    asm("tanh.approx.f32 %0, %1;" : "=f"(y) : "f"(x));
    return y;
}

// ---------------- kernel 1: scatter edges into sector-spread sharded dst buckets ----------------
__global__ void k_bucket(const int* __restrict__ ei,
                         const float* __restrict__ ew, int E) {
    int e = blockIdx.x * blockDim.x + threadIdx.x;
    if (e < NN) g_rs[e] = 0.0f;             // reset before k_dedup accumulates
    if (e >= E) return;
    int src = __ldg(ei + e);
    int dst = __ldg(ei + E + e);
    int sub = e & (NSUB - 1);
    int p = atomicAdd(&g_scnt[(dst * NSUB + sub) * CPAD], 1);   // each counter: own 32B sector
    if (p < SUBCAP) {
        u64 v = ((u64)(unsigned)((src << 18) | e) << 32) | (u64)__float_as_uint(__ldg(ew + e));
        g_bkt[dst * CAP + sub * SUBCAP + p] = v;
    }
}

// ---------------- kernel 2: one warp per dst row: compact, last-write-wins dedup, row sums, CSR ----------------
__global__ void __launch_bounds__(ROWS_PER_BLK * 32) k_dedup() {
    __shared__ u64 sm[ROWS_PER_BLK][CAP];
    __shared__ int s_pos[ROWS_PER_BLK];

    int w    = threadIdx.x >> 5;
    int lane = threadIdx.x & 31;
    int i    = blockIdx.x * ROWS_PER_BLK + w;

    // sub-bucket counts: lane s holds count of sub s; broadcast via shuffle
    int cval = 0;
    if (lane < NSUB) {
        cval = min(g_scnt[(i * NSUB + lane) * CPAD], SUBCAP);
        g_scnt[(i * NSUB + lane) * CPAD] = 0;        // self-clean for next replay
    }
    int c[NSUB], base[NSUB];
    int tot = 0;
    #pragma unroll
    for (int s = 0; s < NSUB; s++) {
        c[s] = __shfl_sync(0xffffffff, cval, s);
        base[s] = tot;
        tot += c[s];
    }
    if (lane == 0) s_pos[w] = 0;

    // dense compaction of ragged sub-buckets into smem
    #pragma unroll
    for (int slot = 0; slot < CAP; slot += 32) {
        int s = (slot + lane) >> 5;                  // sub index of this slot
        int l = (slot + lane) & 31;
        if (l < c[s]) sm[w][base[s] + l] = g_bkt[i * CAP + slot + lane];
    }
    __syncwarp();

    // dedup scan: same src (key>>18), larger packed key (newer edge) wins
    for (int j = lane; j < tot; j += 32) {
        u64 vj = sm[w][j];
        int kj = (int)(vj >> 32);
        bool winner = true;
        for (int k = 0; k < tot; k++) {
            int kk = (int)(sm[w][k] >> 32);
            if (((kk ^ kj) >> 18) == 0 && kk > kj) winner = false;
        }
        if (winner) {
            int src = kj >> 18;
            float wt = __uint_as_float((unsigned)vj);
            atomicAdd(&g_rs[src], wt);               // no-return -> RED, spread addresses
            int pos = atomicAdd(&s_pos[w], 1);       // order irrelevant to the gather
            g_csr[i * CAP + pos] = ((u64)(unsigned)src << 32) | (u64)__float_as_uint(wt);
        }
    }
    __syncwarp();
    if (lane == 0) g_ccnt[i] = s_pos[w];
}

// ---------------- kernel 3: SpMM + tanh epilogue, one block per dst row ----------------
// d[i] = rsqrt(1 + rs[i]);  ax[i,t] = d[i]*( d[i]*x[i,t] + sum w * d[s] * x[s,t] )
// out[i,t,d] = tanh(ax[i,t] * wv[d])
__global__ void __launch_bounds__(128) k_fused(const float* __restrict__ x,
                                               const float* __restrict__ wv,
                                               float4* __restrict__ out) {
    __shared__ int    ss[128];
    __shared__ float  sw[128];
    __shared__ float  s_ax[TT];
    __shared__ float4 s_w[DD / 4];

    int i = blockIdx.x;
    int t = threadIdx.x;
    if (t < DD / 4) s_w[t] = reinterpret_cast<const float4*>(wv)[t];

    int cnt = g_ccnt[i];
    float dinv_i = rsqrtf(1.0f + g_rs[i]);
    float acc = dinv_i * x[i * TT + t];     // self-loop term (outer d[i] applied at end)

    for (int bse = 0; bse < cnt; bse += 128) {
        if (bse + t < cnt) {
            u64 v = g_csr[i * CAP + bse + t];
            int s = (int)(v >> 32);
            ss[t] = s;
            sw[t] = __uint_as_float((unsigned)v) * rsqrtf(1.0f + g_rs[s]);
        }
        __syncthreads();
        int n = min(128, cnt - bse);
        #pragma unroll 4
        for (int j = 0; j < n; j++)
            acc = fmaf(sw[j], x[ss[j] * TT + t], acc);
        __syncthreads();
    }

    s_ax[t] = dinv_i * acc;
    __syncthreads();

    // 128*64 floats = 2048 float4 per row, coalesced streaming stores (evict-first)
    float4* outb = out + (size_t)i * (TT * DD / 4);
    #pragma unroll
    for (int k = t; k < TT * DD / 4; k += 128) {
        float  a  = s_ax[k >> 4];
        float4 w4 = s_w[k & 15];
        float4 r;
        r.x = tanh_fast(a * w4.x);
        r.y = tanh_fast(a * w4.y);
        r.z = tanh_fast(a * w4.z);
        r.w = tanh_fast(a * w4.w);
        __stcs(outb + k, r);
    }
}

extern "C" void kernel_launch(void* const* d_in, const int* in_sizes, int n_in,
                              void* d_out, int out_size) {
    const float* x  = (const float*)d_in[0];   // [4096,128] fp32
    const int*   ei = (const int*)d_in[1];     // [2,E] int32 (JAX x64 disabled)
    const float* ew = (const float*)d_in[2];   // [E] fp32
    const float* wv = (const float*)d_in[3];   // [1,64] fp32

    int E = in_sizes[2];

    k_bucket<<<(E + 255) / 256, 256>>>(ei, ew, E);
    k_dedup<<<NN / ROWS_PER_BLK, ROWS_PER_BLK * 32>>>();
    k_fused<<<NN, 128>>>(x, wv, (float4*)d_out);
    (void)n_in; (void)out_size;
}